// round 16
// baseline (speedup 1.0000x reference)
#include <cuda_runtime.h>
#include <cuda_fp16.h>
#include <math.h>

#define UU 4096
#define II 16384
#define DD 64
#define NNODES (UU + II)   // 20480
#define NEI 524288
#define NES 65536
#define CAP_I 80           // interaction bucket capacity (mean deg 25.6)
#define CAP_S 64           // social bucket capacity (mean deg 16)
#define NB 296             // persistent grid: 2 blocks/SM on >=148 SMs (guaranteed resident)
#define NT (NB * 512)

// ---------------- device scratch (no allocation allowed) ----------------
__device__ __half2 g_e16[NNODES * 32];  // fp16 copy of [user_emb; item_emb]
__device__ __half2 g_h1h[NNODES * 32];  // layer-1 output (fp16)
__device__ __half2 g_h2h[NNODES * 32];  // layer-2 output (fp16)
__device__ float   g_acc[UU * DD];      // running fp32 sum h0+h1+h2 (user rows)
__device__ float   g_ue[UU * DD];       // final lightgcn user embedding (fp32)
__device__ __half2 g_ue16[UU * 32];     // fp16 mirror for social gather

__device__ int    g_cur_i[NNODES + 1];  // bucket counters (reset by k_social tail)
__device__ float2 g_ep[NNODES * CAP_I]; // bucketed interaction rows (col-bits, val)

__device__ int    g_cur_s[UU + 1];      // social counters (reset by k_zero_s_kab)
__device__ float2 g_sp[UU * CAP_S];     // bucketed social rows (col-bits, edge weight)

__device__ float  g_Ka[DD * DD];
__device__ float  g_Kb[DD * DD];
__device__ float  g_Pa[UU * DD];
__device__ float  g_Pb[UU * DD];

__device__ unsigned g_bar[3];           // software grid barriers (reset by k_social tail)

// ======================= chain A: one persistent kernel =======================

__device__ __forceinline__ void grid_bar(int p) {
    __syncthreads();
    if (threadIdx.x == 0) {
        __threadfence();
        unsigned arr = atomicAdd(&g_bar[p], 1u) + 1u;
        while (arr < NB) {
            __nanosleep(200);
            arr = atomicAdd(&g_bar[p], 0u);
        }
        __threadfence();
    }
    __syncthreads();
}

// one warp processes one row (32 lanes x 2 dims), unroll 4
__device__ __forceinline__ void spmm_row(int row, int lane, int layer,
                                         const float2* __restrict__ uin2) {
    const __half2* __restrict__ src =
        (layer == 1) ? g_e16 : (layer == 2 ? g_h1h : g_h2h);
    float2* __restrict__ acc2 = (float2*)g_acc;

    int b = row * CAP_I;
    int e = b + min(g_cur_i[row], CAP_I);
    float ax = 0.f, ay = 0.f;

    int k = b;
    for (; k + 3 < e; k += 4) {
        float2 e0 = g_ep[k],     e1 = g_ep[k + 1];
        float2 e2 = g_ep[k + 2], e3 = g_ep[k + 3];
        float2 x0 = __half22float2(src[__float_as_int(e0.x) * 32 + lane]);
        float2 x1 = __half22float2(src[__float_as_int(e1.x) * 32 + lane]);
        float2 x2 = __half22float2(src[__float_as_int(e2.x) * 32 + lane]);
        float2 x3 = __half22float2(src[__float_as_int(e3.x) * 32 + lane]);
        ax += e0.y * x0.x; ay += e0.y * x0.y;
        ax += e1.y * x1.x; ay += e1.y * x1.y;
        ax += e2.y * x2.x; ay += e2.y * x2.y;
        ax += e3.y * x3.x; ay += e3.y * x3.y;
    }
    for (; k < e; k++) {
        float2 ev = g_ep[k];
        float2 x = __half22float2(src[__float_as_int(ev.x) * 32 + lane]);
        ax += ev.y * x.x; ay += ev.y * x.y;
    }

    int o = row * 32 + lane;
    if (layer == 1) {
        g_h1h[o] = __floats2half2_rn(ax, ay);
        if (row < UU) {
            float2 u = uin2[o];
            acc2[o] = make_float2(u.x + ax, u.y + ay);
        }
    } else if (layer == 2) {
        g_h2h[o] = __floats2half2_rn(ax, ay);
        if (row < UU) {
            float2 a = acc2[o];
            acc2[o] = make_float2(a.x + ax, a.y + ay);
        }
    } else {
        float2 a = acc2[o];
        float2 u = make_float2((a.x + ax) * 0.25f, (a.y + ay) * 0.25f);
        ((float2*)g_ue)[o] = u;
        g_ue16[o] = __floats2half2_rn(u.x, u.y);
    }
}

__global__ void __launch_bounds__(512, 2) k_fusedA(
    const float2* __restrict__ uin2, const float2* __restrict__ iin2,
    const int* __restrict__ irows, const int* __restrict__ icols,
    const float* __restrict__ ivals)
{
    int tid = threadIdx.x;
    int gt = blockIdx.x * 512 + tid;

    // phase 0a: fp16 conversion of inputs
    for (int t = gt; t < NNODES * 32; t += NT) {
        float2 v = (t < UU * 32) ? uin2[t] : iin2[t - UU * 32];
        g_e16[t] = __floats2half2_rn(v.x, v.y);
    }
    // phase 0b: direct bucket scatter (no histogram, no scan)
    for (int e = gt; e < NEI; e += NT) {
        int r = irows[e];
        int p = atomicAdd(&g_cur_i[r], 1);
        if (p < CAP_I)
            g_ep[r * CAP_I + p] = make_float2(__int_as_float(icols[e]), ivals[e]);
    }
    grid_bar(0);

    int w = tid >> 5, lane = tid & 31;
    int gw = blockIdx.x * 16 + w;          // 0..4735 warps

    for (int row = gw; row < NNODES; row += NB * 16) spmm_row(row, lane, 1, uin2);
    grid_bar(1);
    for (int row = gw; row < NNODES; row += NB * 16) spmm_row(row, lane, 2, uin2);
    grid_bar(2);
    for (int row = gw; row < UU; row += NB * 16) spmm_row(row, lane, 3, uin2);
}

// ======================= chain B: social graph =======================

__global__ void k_zero_s_kab(const float* __restrict__ Wa, const float* __restrict__ Wb,
                             const float* __restrict__ w1) {
    int b = blockIdx.x;
    if (b < 17) {
        int t = b * 256 + threadIdx.x;
        if (t <= UU) g_cur_s[t] = 0;
    } else {
        int t = (b - 17) * 256 + threadIdx.x;   // 0..8191
        int which = t >> 12;
        int idx = t & 4095;
        int k = idx >> 6, j = idx & 63;
        const float* W = which ? Wb : Wa;
        const float* w1p = which ? (w1 + 64 * 64) : w1;
        float s = 0.f;
#pragma unroll 8
        for (int m = 0; m < 64; m++) s += W[k * 64 + m] * w1p[m * 64 + j];
        if (which) g_Kb[idx] = s; else g_Ka[idx] = s;
    }
}

__global__ void k_pab(const float* __restrict__ ue_in, const float* __restrict__ b1) {
    __shared__ float sKa[64 * 64];
    __shared__ float sKb[64 * 64];
    int t = threadIdx.x;
    for (int q = t; q < 4096; q += 256) { sKa[q] = g_Ka[q]; sKb[q] = g_Kb[q]; }
    __syncthreads();
    int j = t & 63;
    int isub = t >> 6;
    int i0 = blockIdx.x * 16;   // 256 blocks x 16 rows
    for (int ii = isub; ii < 16; ii += 4) {
        int i = i0 + ii;
        float a = 0.f, bb = 0.f;
#pragma unroll 8
        for (int k = 0; k < 64; k++) {
            float u = ue_in[i * 64 + k];
            a += u * sKa[k * 64 + j];
            bb += u * sKb[k * 64 + j];
        }
        g_Pa[i * 64 + j] = a;
        g_Pb[i * 64 + j] = bb + b1[j];
    }
}

// edge MLP (one warp per edge) + direct bucket scatter on lane 0
__global__ void k_edge_scatter(const int* __restrict__ srows, const int* __restrict__ scols,
                               const float* __restrict__ w2, const float* __restrict__ b2) {
    int lane = threadIdx.x & 31;
    int wg = blockIdx.x * 32 + (threadIdx.x >> 5);   // 256 blocks * 32 warps = 8192
    const float2* __restrict__ Pa2 = (const float2*)g_Pa;
    const float2* __restrict__ Pb2 = (const float2*)g_Pb;
    float2 wv = ((const float2*)w2)[lane];
    float bias = b2[0];
    for (int e = wg; e < NES; e += 8192) {
        int r = srows[e], c = scols[e];
        float2 pa = Pa2[c * 32 + lane];
        float2 pb = Pb2[r * 32 + lane];
        float h0 = fmaxf(pa.x + pb.x, 0.f);
        float h1 = fmaxf(pa.y + pb.y, 0.f);
        float pv = h0 * wv.x + h1 * wv.y;
#pragma unroll
        for (int o = 16; o; o >>= 1) pv += __shfl_down_sync(0xffffffffu, pv, o);
        if (lane == 0) {
            float ew = 1.f / (1.f + __expf(-(pv + bias)));
            int p = atomicAdd(&g_cur_s[r], 1);
            if (p < CAP_S)
                g_sp[(r << 6) + p] = make_float2(__int_as_float(c), ew);
        }
    }
}

// ======================= join: social propagation (R12 version) =======================

__global__ void __launch_bounds__(512) k_social(float2* __restrict__ out2) {
    __shared__ float rA[UU];             // 16 KB
    __shared__ float rA2[UU];            // 16 KB
    __shared__ unsigned short lst[UU];   // 8 KB
    __shared__ int nlst;
    __shared__ float wr1[16], wr2[16];
    __shared__ float bc1, bc2;
    __shared__ float2 sg[16][32];        // 4 KB

    int i = blockIdx.x;
    int t = threadIdx.x;   // 512
    int lane = t & 31, w = t >> 5;

    float4* rA4 = (float4*)rA;
    float4* rB4 = (float4*)rA2;
    float4 z4 = make_float4(0.f, 0.f, 0.f, 0.f);
#pragma unroll
    for (int q = t; q < UU / 4; q += 512) { rA4[q] = z4; rB4[q] = z4; }
    if (t == 0) nlst = 0;
    __syncthreads();

    int b = i << 6;
    int e = b + min(g_cur_s[i], CAP_S);
    // depth-1 merged row (packed load)
    for (int k = b + t; k < e; k += 512) {
        float2 sp = g_sp[k];
        atomicAdd(&rA[__float_as_int(sp.x)], sp.y);
    }
    // depth-2: 16 threads per neighbor, packed loads
    for (int k = b + (t >> 4); k < e; k += 32) {
        float2 sp = g_sp[k];
        int kk = __float_as_int(sp.x);
        float wv = sp.y;
        int b2i = kk << 6;
        int e2i = b2i + min(g_cur_s[kk], CAP_S);
        for (int m = b2i + (t & 15); m < e2i; m += 16) {
            float2 sp2 = g_sp[m];
            atomicAdd(&rA2[__float_as_int(sp2.x)], wv * sp2.y);
        }
    }
    __syncthreads();

    // compaction fused with max computation
    float m1 = -1e30f, m2 = -1e30f;
#pragma unroll
    for (int j = t; j < UU; j += 512) {
        float a1 = rA[j], a2 = rA2[j];
        bool nz = (a1 > 0.f) || (a2 > 0.f);
        m1 = fmaxf(m1, a1 > 0.f ? a1 : -1e30f);
        m2 = fmaxf(m2, a2 > 0.f ? a2 : -1e30f);
        unsigned mask = __ballot_sync(0xffffffffu, nz);
        if (nz) {
            int lead = __ffs(mask) - 1;
            int basep = 0;
            if (lane == lead) basep = atomicAdd(&nlst, __popc(mask));
            basep = __shfl_sync(mask, basep, lead);
            int off = __popc(mask & ((1u << lane) - 1u));
            lst[basep + off] = (unsigned short)j;
        }
    }
#pragma unroll
    for (int o = 16; o; o >>= 1) {
        m1 = fmaxf(m1, __shfl_xor_sync(0xffffffffu, m1, o));
        m2 = fmaxf(m2, __shfl_xor_sync(0xffffffffu, m2, o));
    }
    if (lane == 0) { wr1[w] = m1; wr2[w] = m2; }
    __syncthreads();
    if (w == 0 && lane < 16) {
        m1 = wr1[lane]; m2 = wr2[lane];
#pragma unroll
        for (int o = 8; o; o >>= 1) {
            m1 = fmaxf(m1, __shfl_xor_sync(0xffffu, m1, o));
            m2 = fmaxf(m2, __shfl_xor_sync(0xffffu, m2, o));
        }
        if (lane == 0) { bc1 = m1; bc2 = m2; }
    }
    __syncthreads();
    m1 = bc1; m2 = bc2;
    int L = nlst;
    __syncthreads();

    // exp + sums (writeback; list entries unique)
    float s1 = 0.f, s2 = 0.f;
    for (int q = t; q < L; q += 512) {
        int j = lst[q];
        float a1 = rA[j], a2 = rA2[j];
        float e1 = (a1 > 0.f) ? __expf(a1 - m1) : 0.f;
        float e2 = (a2 > 0.f) ? __expf(a2 - m2) : 0.f;
        rA[j] = e1; rA2[j] = e2;
        s1 += e1; s2 += e2;
    }
#pragma unroll
    for (int o = 16; o; o >>= 1) {
        s1 += __shfl_xor_sync(0xffffffffu, s1, o);
        s2 += __shfl_xor_sync(0xffffffffu, s2, o);
    }
    if (lane == 0) { wr1[w] = s1; wr2[w] = s2; }
    __syncthreads();
    if (w == 0 && lane < 16) {
        s1 = wr1[lane]; s2 = wr2[lane];
#pragma unroll
        for (int o = 8; o; o >>= 1) {
            s1 += __shfl_xor_sync(0xffffu, s1, o);
            s2 += __shfl_xor_sync(0xffffu, s2, o);
        }
        if (lane == 0) { bc1 = s1; bc2 = s2; }
    }
    __syncthreads();
    float inv1 = (bc1 > 0.f) ? 1.f / bc1 : 0.f;
    float inv2 = (bc2 > 0.f) ? 1.f / bc2 : 0.f;

    // combine both softmaxes into ONE weight per column
    for (int q = t; q < L; q += 512) {
        int j = lst[q];
        rA[j] = rA[j] * inv1 + rA2[j] * inv2;
    }
    __syncthreads();

    // weighted accumulation over list from fp16 ue; 16 warps x 32 lanes, unroll 4
    float2 o1 = make_float2(0.f, 0.f);
    int q = w;
    for (; q + 48 < L; q += 64) {
        int j0 = lst[q], j1 = lst[q + 16], j2 = lst[q + 32], j3 = lst[q + 48];
        float2 u0 = __half22float2(g_ue16[j0 * 32 + lane]);
        float2 u1 = __half22float2(g_ue16[j1 * 32 + lane]);
        float2 u2 = __half22float2(g_ue16[j2 * 32 + lane]);
        float2 u3 = __half22float2(g_ue16[j3 * 32 + lane]);
        float p0 = rA[j0], p1 = rA[j1], p2 = rA[j2], p3 = rA[j3];
        o1.x += p0 * u0.x; o1.y += p0 * u0.y;
        o1.x += p1 * u1.x; o1.y += p1 * u1.y;
        o1.x += p2 * u2.x; o1.y += p2 * u2.y;
        o1.x += p3 * u3.x; o1.y += p3 * u3.y;
    }
    for (; q < L; q += 16) {
        int j = lst[q];
        float2 u = __half22float2(g_ue16[j * 32 + lane]);
        float p = rA[j];
        o1.x += p * u.x; o1.y += p * u.y;
    }
    sg[w][lane] = o1;
    __syncthreads();
    if (t < 32) {
        float tx = 0.f, ty = 0.f;
#pragma unroll
        for (int gg = 0; gg < 16; gg++) { tx += sg[gg][lane].x; ty += sg[gg][lane].y; }
        float2 u = ((const float2*)g_ue)[i * 32 + lane];
        out2[i * 32 + lane] = make_float2(
            (4.f / 3.f) * u.x + tx * (1.f / 3.f),
            (4.f / 3.f) * u.y + ty * (1.f / 3.f));
    }

    // reset interaction bucket counters + grid barriers for the next replay.
    int gi = i * 512 + t;
    if (gi <= NNODES) g_cur_i[gi] = 0;
    if (i == 0 && t < 3) g_bar[t] = 0;
}

// ---------------- launch: two-stream fork/join DAG ----------------
extern "C" void kernel_launch(void* const* d_in, const int* in_sizes, int n_in,
                              void* d_out, int out_size) {
    const float* ue_in = (const float*)d_in[0];
    const float* ie_in = (const float*)d_in[1];
    const float* ivals = (const float*)d_in[2];
    const float* Wa    = (const float*)d_in[3];
    const float* Wb    = (const float*)d_in[4];
    const float* w1    = (const float*)d_in[5];
    const float* b1    = (const float*)d_in[6];
    const float* w2    = (const float*)d_in[7];
    const float* b2    = (const float*)d_in[8];
    const int* irows   = (const int*)d_in[9];
    const int* icols   = (const int*)d_in[10];
    const int* srows   = (const int*)d_in[11];
    const int* scols   = (const int*)d_in[12];

    static cudaStream_t sB = nullptr;
    static cudaEvent_t evFork = nullptr, evJoinB = nullptr;
    if (sB == nullptr) {
        cudaStreamCreateWithFlags(&sB, cudaStreamNonBlocking);
        cudaEventCreateWithFlags(&evFork, cudaEventDisableTiming);
        cudaEventCreateWithFlags(&evJoinB, cudaEventDisableTiming);
    }

    // fork
    cudaEventRecord(evFork, 0);
    cudaStreamWaitEvent(sB, evFork, 0);

    // chain B: social edge weights + bucketed CSR (hidden under chain A)
    k_zero_s_kab<<<17 + 32, 256, 0, sB>>>(Wa, Wb, w1);
    k_pab<<<256, 256, 0, sB>>>(ue_in, b1);
    k_edge_scatter<<<256, 1024, 0, sB>>>(srows, scols, w2, b2);
    cudaEventRecord(evJoinB, sB);

    // chain A: one persistent kernel (cvt + scatter + 3 SpMM layers)
    k_fusedA<<<NB, 512>>>((const float2*)ue_in, (const float2*)ie_in,
                          irows, icols, ivals);

    // join, then social propagation
    cudaStreamWaitEvent(0, evJoinB, 0);
    k_social<<<UU, 512>>>((float2*)d_out);
}

// round 17
// speedup vs baseline: 1.4067x; 1.4067x over previous
#include <cuda_runtime.h>
#include <cuda_fp16.h>
#include <math.h>

#define UU 4096
#define II 16384
#define DD 64
#define NNODES (UU + II)   // 20480
#define NEI 524288
#define NES 65536
#define CAP_I 80           // interaction bucket capacity (mean deg 25.6)
#define CAP_S 64           // social bucket capacity (mean deg 16)
#define CAP_L 1024         // per-row softmax list capacity (union ~270, >40 sigma margin)

// ---------------- device scratch (no allocation allowed) ----------------
__device__ __half2 g_e16[NNODES * 32];  // fp16 copy of [user_emb; item_emb]
__device__ __half2 g_h1h[NNODES * 32];  // layer-1 output (fp16)
__device__ __half2 g_h2h[NNODES * 32];  // layer-2 output (fp16)
__device__ float   g_acc[UU * DD];      // running fp32 sum h0+h1+h2 (user rows)
__device__ float   g_ue[UU * DD];       // final lightgcn user embedding (fp32)
__device__ __half2 g_ue16[UU * 32];     // fp16 mirror for social gather

__device__ int    g_cur_i[NNODES + 1];  // bucket counters (reset by k_gather tail)
__device__ float2 g_ep[NNODES * CAP_I]; // bucketed interaction rows (col-bits, val)

__device__ int    g_cur_s[UU + 1];      // social counters (reset by k_zero_s_kab)
__device__ float2 g_sp[UU * CAP_S];     // bucketed social rows (col-bits, edge weight)

__device__ int    g_ln[UU];             // per-row softmax list length
__device__ float2 g_lw[UU * CAP_L];     // per-row (col-bits, combined weight)

__device__ float  g_Ka[DD * DD];
__device__ float  g_Kb[DD * DD];
__device__ float  g_Pa[UU * DD];
__device__ float  g_Pb[UU * DD];

// ===== chain C: input fp16 conversion =====
__global__ void k_cvt(const float2* __restrict__ uin2, const float2* __restrict__ iin2) {
    int t = blockIdx.x * blockDim.x + threadIdx.x;
    if (t < UU * 32) {
        float2 v = uin2[t];
        g_e16[t] = __floats2half2_rn(v.x, v.y);
    } else if (t < NNODES * 32) {
        float2 v = iin2[t - UU * 32];
        g_e16[t] = __floats2half2_rn(v.x, v.y);
    }
}

// ======================= chain A: interaction graph =======================

// direct bucket scatter: no histogram, no scan
__global__ void k_scatter_i(const int* __restrict__ irows, const int* __restrict__ icols,
                            const float* __restrict__ ivals) {
    int e = blockIdx.x * 256 + threadIdx.x;   // 2048 blocks: one edge per thread
    if (e < NEI) {
        int r = irows[e];
        int p = atomicAdd(&g_cur_i[r], 1);
        if (p < CAP_I)
            g_ep[r * CAP_I + p] = make_float2(__int_as_float(icols[e]), ivals[e]);
    }
}

// SpMM: 32 lanes x 2 dims per row, 8 rows/block, unroll 4
template <int LAYER>
__global__ void k_spmm(const float2* __restrict__ uin2) {
    int row = blockIdx.x * 8 + threadIdx.y;
    int lane = threadIdx.x;
    float2* __restrict__ acc2 = (float2*)g_acc;

    int b = row * CAP_I;
    int e = b + min(g_cur_i[row], CAP_I);
    float ax = 0.f, ay = 0.f;

    auto fetch = [&](int c) -> float2 {
        if (LAYER == 1) return __half22float2(g_e16[c * 32 + lane]);
        else if (LAYER == 2) return __half22float2(g_h1h[c * 32 + lane]);
        else return __half22float2(g_h2h[c * 32 + lane]);
    };

    int k = b;
    for (; k + 3 < e; k += 4) {
        float2 e0 = g_ep[k],     e1 = g_ep[k + 1];
        float2 e2 = g_ep[k + 2], e3 = g_ep[k + 3];
        float2 x0 = fetch(__float_as_int(e0.x));
        float2 x1 = fetch(__float_as_int(e1.x));
        float2 x2 = fetch(__float_as_int(e2.x));
        float2 x3 = fetch(__float_as_int(e3.x));
        ax += e0.y * x0.x; ay += e0.y * x0.y;
        ax += e1.y * x1.x; ay += e1.y * x1.y;
        ax += e2.y * x2.x; ay += e2.y * x2.y;
        ax += e3.y * x3.x; ay += e3.y * x3.y;
    }
    for (; k < e; k++) {
        float2 ev = g_ep[k];
        float2 x = fetch(__float_as_int(ev.x));
        ax += ev.y * x.x; ay += ev.y * x.y;
    }

    int o = row * 32 + lane;
    if (LAYER == 1) {
        g_h1h[o] = __floats2half2_rn(ax, ay);
        if (row < UU) {
            float2 u = uin2[o];
            acc2[o] = make_float2(u.x + ax, u.y + ay);
        }
    } else if (LAYER == 2) {
        g_h2h[o] = __floats2half2_rn(ax, ay);
        if (row < UU) {
            float2 a = acc2[o];
            acc2[o] = make_float2(a.x + ax, a.y + ay);
        }
    } else {
        // user rows only (grid = UU/8)
        float2 a = acc2[o];
        float2 u = make_float2((a.x + ax) * 0.25f, (a.y + ay) * 0.25f);
        ((float2*)g_ue)[o] = u;
        g_ue16[o] = __floats2half2_rn(u.x, u.y);
    }
}

// ======================= chain B: social graph =======================

__global__ void k_zero_s_kab(const float* __restrict__ Wa, const float* __restrict__ Wb,
                             const float* __restrict__ w1) {
    int b = blockIdx.x;
    if (b < 17) {
        int t = b * 256 + threadIdx.x;
        if (t <= UU) g_cur_s[t] = 0;
    } else {
        int t = (b - 17) * 256 + threadIdx.x;   // 0..8191
        int which = t >> 12;
        int idx = t & 4095;
        int k = idx >> 6, j = idx & 63;
        const float* W = which ? Wb : Wa;
        const float* w1p = which ? (w1 + 64 * 64) : w1;
        float s = 0.f;
#pragma unroll 8
        for (int m = 0; m < 64; m++) s += W[k * 64 + m] * w1p[m * 64 + j];
        if (which) g_Kb[idx] = s; else g_Ka[idx] = s;
    }
}

__global__ void k_pab(const float* __restrict__ ue_in, const float* __restrict__ b1) {
    __shared__ float sKa[64 * 64];
    __shared__ float sKb[64 * 64];
    int t = threadIdx.x;
    for (int q = t; q < 4096; q += 256) { sKa[q] = g_Ka[q]; sKb[q] = g_Kb[q]; }
    __syncthreads();
    int j = t & 63;
    int isub = t >> 6;
    int i0 = blockIdx.x * 16;   // 256 blocks x 16 rows
    for (int ii = isub; ii < 16; ii += 4) {
        int i = i0 + ii;
        float a = 0.f, bb = 0.f;
#pragma unroll 8
        for (int k = 0; k < 64; k++) {
            float u = ue_in[i * 64 + k];
            a += u * sKa[k * 64 + j];
            bb += u * sKb[k * 64 + j];
        }
        g_Pa[i * 64 + j] = a;
        g_Pb[i * 64 + j] = bb + b1[j];
    }
}

// edge MLP (one warp per edge) + direct bucket scatter on lane 0
__global__ void k_edge_scatter(const int* __restrict__ srows, const int* __restrict__ scols,
                               const float* __restrict__ w2, const float* __restrict__ b2) {
    int lane = threadIdx.x & 31;
    int wg = blockIdx.x * 32 + (threadIdx.x >> 5);   // 256 blocks * 32 warps = 8192
    const float2* __restrict__ Pa2 = (const float2*)g_Pa;
    const float2* __restrict__ Pb2 = (const float2*)g_Pb;
    float2 wv = ((const float2*)w2)[lane];
    float bias = b2[0];
    for (int e = wg; e < NES; e += 8192) {
        int r = srows[e], c = scols[e];
        float2 pa = Pa2[c * 32 + lane];
        float2 pb = Pb2[r * 32 + lane];
        float h0 = fmaxf(pa.x + pb.x, 0.f);
        float h1 = fmaxf(pa.y + pb.y, 0.f);
        float pv = h0 * wv.x + h1 * wv.y;
#pragma unroll
        for (int o = 16; o; o >>= 1) pv += __shfl_down_sync(0xffffffffu, pv, o);
        if (lane == 0) {
            float ew = 1.f / (1.f + __expf(-(pv + bias)));
            int p = atomicAdd(&g_cur_s[r], 1);
            if (p < CAP_S)
                g_sp[(r << 6) + p] = make_float2(__int_as_float(c), ew);
        }
    }
}

// softmax weights (build + compact + both softmaxes), writes (col, weight) list.
// Depends ONLY on the social CSR -> runs on stream B, concurrent with SpMM.
__global__ void __launch_bounds__(512) k_social_w() {
    __shared__ float rA[UU];             // 16 KB
    __shared__ float rA2[UU];            // 16 KB
    __shared__ unsigned short lst[UU];   // 8 KB
    __shared__ int nlst;
    __shared__ float wr1[16], wr2[16];
    __shared__ float bc1, bc2;

    int i = blockIdx.x;
    int t = threadIdx.x;   // 512
    int lane = t & 31, w = t >> 5;

    float4* rA4 = (float4*)rA;
    float4* rB4 = (float4*)rA2;
    float4 z4 = make_float4(0.f, 0.f, 0.f, 0.f);
#pragma unroll
    for (int q = t; q < UU / 4; q += 512) { rA4[q] = z4; rB4[q] = z4; }
    if (t == 0) nlst = 0;
    __syncthreads();

    int b = i << 6;
    int e = b + min(g_cur_s[i], CAP_S);
    // depth-1 merged row (packed load)
    for (int k = b + t; k < e; k += 512) {
        float2 sp = g_sp[k];
        atomicAdd(&rA[__float_as_int(sp.x)], sp.y);
    }
    // depth-2: 16 threads per neighbor, packed loads
    for (int k = b + (t >> 4); k < e; k += 32) {
        float2 sp = g_sp[k];
        int kk = __float_as_int(sp.x);
        float wv = sp.y;
        int b2i = kk << 6;
        int e2i = b2i + min(g_cur_s[kk], CAP_S);
        for (int m = b2i + (t & 15); m < e2i; m += 16) {
            float2 sp2 = g_sp[m];
            atomicAdd(&rA2[__float_as_int(sp2.x)], wv * sp2.y);
        }
    }
    __syncthreads();

    // compaction fused with max computation
    float m1 = -1e30f, m2 = -1e30f;
#pragma unroll
    for (int j = t; j < UU; j += 512) {
        float a1 = rA[j], a2 = rA2[j];
        bool nz = (a1 > 0.f) || (a2 > 0.f);
        m1 = fmaxf(m1, a1 > 0.f ? a1 : -1e30f);
        m2 = fmaxf(m2, a2 > 0.f ? a2 : -1e30f);
        unsigned mask = __ballot_sync(0xffffffffu, nz);
        if (nz) {
            int lead = __ffs(mask) - 1;
            int basep = 0;
            if (lane == lead) basep = atomicAdd(&nlst, __popc(mask));
            basep = __shfl_sync(mask, basep, lead);
            int off = __popc(mask & ((1u << lane) - 1u));
            lst[basep + off] = (unsigned short)j;
        }
    }
#pragma unroll
    for (int o = 16; o; o >>= 1) {
        m1 = fmaxf(m1, __shfl_xor_sync(0xffffffffu, m1, o));
        m2 = fmaxf(m2, __shfl_xor_sync(0xffffffffu, m2, o));
    }
    if (lane == 0) { wr1[w] = m1; wr2[w] = m2; }
    __syncthreads();
    if (w == 0 && lane < 16) {
        m1 = wr1[lane]; m2 = wr2[lane];
#pragma unroll
        for (int o = 8; o; o >>= 1) {
            m1 = fmaxf(m1, __shfl_xor_sync(0xffffu, m1, o));
            m2 = fmaxf(m2, __shfl_xor_sync(0xffffu, m2, o));
        }
        if (lane == 0) { bc1 = m1; bc2 = m2; }
    }
    __syncthreads();
    m1 = bc1; m2 = bc2;
    int L = nlst;
    __syncthreads();

    // exp + sums (writeback; list entries unique)
    float s1 = 0.f, s2 = 0.f;
    for (int q = t; q < L; q += 512) {
        int j = lst[q];
        float a1 = rA[j], a2 = rA2[j];
        float e1 = (a1 > 0.f) ? __expf(a1 - m1) : 0.f;
        float e2 = (a2 > 0.f) ? __expf(a2 - m2) : 0.f;
        rA[j] = e1; rA2[j] = e2;
        s1 += e1; s2 += e2;
    }
#pragma unroll
    for (int o = 16; o; o >>= 1) {
        s1 += __shfl_xor_sync(0xffffffffu, s1, o);
        s2 += __shfl_xor_sync(0xffffffffu, s2, o);
    }
    if (lane == 0) { wr1[w] = s1; wr2[w] = s2; }
    __syncthreads();
    if (w == 0 && lane < 16) {
        s1 = wr1[lane]; s2 = wr2[lane];
#pragma unroll
        for (int o = 8; o; o >>= 1) {
            s1 += __shfl_xor_sync(0xffffu, s1, o);
            s2 += __shfl_xor_sync(0xffffu, s2, o);
        }
        if (lane == 0) { bc1 = s1; bc2 = s2; }
    }
    __syncthreads();
    float inv1 = (bc1 > 0.f) ? 1.f / bc1 : 0.f;
    float inv2 = (bc2 > 0.f) ? 1.f / bc2 : 0.f;

    // write compacted (col, combined weight) list to global
    for (int q = t; q < L && q < CAP_L; q += 512) {
        int j = lst[q];
        g_lw[(i << 10) + q] =
            make_float2(__int_as_float(j), rA[j] * inv1 + rA2[j] * inv2);
    }
    if (t == 0) g_ln[i] = min(L, CAP_L);
}

// ======================= join: weighted gather only =======================

__global__ void __launch_bounds__(256) k_gather(float2* __restrict__ out2) {
    __shared__ float2 sg[8][32];   // 2 KB -> high occupancy

    int i = blockIdx.x;
    int t = threadIdx.x;   // 256
    int lane = t & 31, w = t >> 5;
    int L = g_ln[i];
    const float2* __restrict__ lw = g_lw + (i << 10);

    float2 o1 = make_float2(0.f, 0.f);
    int q = w;
    for (; q + 24 < L; q += 32) {
        float2 l0 = lw[q],      l1 = lw[q + 8];
        float2 l2 = lw[q + 16], l3 = lw[q + 24];
        float2 u0 = __half22float2(g_ue16[__float_as_int(l0.x) * 32 + lane]);
        float2 u1 = __half22float2(g_ue16[__float_as_int(l1.x) * 32 + lane]);
        float2 u2 = __half22float2(g_ue16[__float_as_int(l2.x) * 32 + lane]);
        float2 u3 = __half22float2(g_ue16[__float_as_int(l3.x) * 32 + lane]);
        o1.x += l0.y * u0.x; o1.y += l0.y * u0.y;
        o1.x += l1.y * u1.x; o1.y += l1.y * u1.y;
        o1.x += l2.y * u2.x; o1.y += l2.y * u2.y;
        o1.x += l3.y * u3.x; o1.y += l3.y * u3.y;
    }
    for (; q < L; q += 8) {
        float2 l = lw[q];
        float2 u = __half22float2(g_ue16[__float_as_int(l.x) * 32 + lane]);
        o1.x += l.y * u.x; o1.y += l.y * u.y;
    }
    sg[w][lane] = o1;
    __syncthreads();
    if (t < 32) {
        float tx = 0.f, ty = 0.f;
#pragma unroll
        for (int gg = 0; gg < 8; gg++) { tx += sg[gg][lane].x; ty += sg[gg][lane].y; }
        float2 u = ((const float2*)g_ue)[i * 32 + lane];
        out2[i * 32 + lane] = make_float2(
            (4.f / 3.f) * u.x + tx * (1.f / 3.f),
            (4.f / 3.f) * u.y + ty * (1.f / 3.f));
    }

    // reset interaction bucket counters for the next graph replay
    int gi = i * 256 + t;
    if (gi <= NNODES) g_cur_i[gi] = 0;
}

// ---------------- launch: three-stream fork/join DAG ----------------
extern "C" void kernel_launch(void* const* d_in, const int* in_sizes, int n_in,
                              void* d_out, int out_size) {
    const float* ue_in = (const float*)d_in[0];
    const float* ie_in = (const float*)d_in[1];
    const float* ivals = (const float*)d_in[2];
    const float* Wa    = (const float*)d_in[3];
    const float* Wb    = (const float*)d_in[4];
    const float* w1    = (const float*)d_in[5];
    const float* b1    = (const float*)d_in[6];
    const float* w2    = (const float*)d_in[7];
    const float* b2    = (const float*)d_in[8];
    const int* irows   = (const int*)d_in[9];
    const int* icols   = (const int*)d_in[10];
    const int* srows   = (const int*)d_in[11];
    const int* scols   = (const int*)d_in[12];

    static cudaStream_t sB = nullptr, sC = nullptr;
    static cudaEvent_t evFork = nullptr, evJoinB = nullptr, evJoinC = nullptr;
    if (sB == nullptr) {
        cudaStreamCreateWithFlags(&sB, cudaStreamNonBlocking);
        cudaStreamCreateWithFlags(&sC, cudaStreamNonBlocking);
        cudaEventCreateWithFlags(&evFork, cudaEventDisableTiming);
        cudaEventCreateWithFlags(&evJoinB, cudaEventDisableTiming);
        cudaEventCreateWithFlags(&evJoinC, cudaEventDisableTiming);
    }

    // fork
    cudaEventRecord(evFork, 0);
    cudaStreamWaitEvent(sB, evFork, 0);
    cudaStreamWaitEvent(sC, evFork, 0);

    // chain C: fp16 conversion of inputs (hidden under scatter_i)
    k_cvt<<<(NNODES * 32 + 255) / 256, 256, 0, sC>>>((const float2*)ue_in, (const float2*)ie_in);
    cudaEventRecord(evJoinC, sC);

    // chain B: edge weights + social CSR + softmax weight lists (hidden under chain A)
    k_zero_s_kab<<<17 + 32, 256, 0, sB>>>(Wa, Wb, w1);
    k_pab<<<256, 256, 0, sB>>>(ue_in, b1);
    k_edge_scatter<<<256, 1024, 0, sB>>>(srows, scols, w2, b2);
    k_social_w<<<UU, 512, 0, sB>>>();
    cudaEventRecord(evJoinB, sB);

    // chain A: bucket scatter (starts immediately) + LightGCN
    k_scatter_i<<<2048, 256>>>(irows, icols, ivals);
    cudaStreamWaitEvent(0, evJoinC, 0);   // e16 ready
    k_spmm<1><<<NNODES / 8, dim3(32, 8)>>>((const float2*)ue_in);
    k_spmm<2><<<NNODES / 8, dim3(32, 8)>>>((const float2*)ue_in);
    k_spmm<3><<<UU / 8,     dim3(32, 8)>>>((const float2*)ue_in);

    // join, then weighted gather only
    cudaStreamWaitEvent(0, evJoinB, 0);
    k_gather<<<UU, 256>>>((float2*)d_out);
}